// round 2
// baseline (speedup 1.0000x reference)
#include <cuda_runtime.h>
#include <math.h>

// Problem constants (fixed by the dataset)
#define NN   100000   // entities
#define DD   300      // e_hidden
#define EE   400000   // triples (KG1)
#define EA   800000   // symmetric all-edge count (2*EH)
#define RRR  2000     // relations
#define RH   100      // r_hidden
#define LG   60000    // line-graph edges

static const int TPB = 256;

// ---------------- device scratch (static globals; no allocation) -------------
__device__ float g_x   [(size_t)NN*DD];   // current entity features
__device__ float g_t   [(size_t)NN*DD];   // GEMM output (xw / gate pre-sigmoid)
__device__ float g_agg [(size_t)NN*DD];   // aggregation accumulator
__device__ float g_deg [NN];
__device__ float g_dinv[NN];
__device__ float g_enorm[EA];             // per-edge gcn norm (reused both layers)
__device__ float g_pA  [NN];              // per-node projections
__device__ float g_pB  [NN];
__device__ int   g_mx  [NN];              // segment max (encoded)
__device__ float g_sm  [NN];              // segment sum
__device__ float g_ew  [EA];              // per-edge scratch (scores -> p -> alpha)
__device__ float g_vi  [LG];
__device__ float g_vj  [LG];
__device__ float g_v2  [LG];
__device__ float g_al  [LG];
__device__ int   g_rmx [RRR];
__device__ float g_rsm [RRR];
__device__ float g_relA[RRR*RH];          // rel_merge
__device__ float g_relB[RRR*RH];          // rel_tri
__device__ float g_rgate[RRR*RH];
__device__ float g_xr  [RRR*RH];          // highway(rel_merge, rel_tri)
__device__ float g_projR2[2*RRR];         // (rel_emb @ a_r) for GAT
__device__ float g_projR3[RRR];           // (x_r @ g2e_ar)

// ---------------- helpers ----------------------------------------------------
__device__ __forceinline__ int encf(float f) {
    int i = __float_as_int(f);
    return i >= 0 ? i : (i ^ 0x7fffffff);
}
__device__ __forceinline__ float decf(int i) {
    return __int_as_float(i >= 0 ? i : (i ^ 0x7fffffff));
}
// 16B vector atomic add (sm_90+); all destinations proven 16B-aligned.
__device__ __forceinline__ void red4(float* p, float a, float b, float c, float d) {
    asm volatile("red.global.add.v4.f32 [%0], {%1, %2, %3, %4};"
                 :: "l"(p), "f"(a), "f"(b), "f"(c), "f"(d) : "memory");
}

// ---------------- elementwise / init -----------------------------------------
__global__ void k_zero(float* p, long long n) {
    long long i = blockIdx.x * (long long)blockDim.x + threadIdx.x;
    if (i < n) p[i] = 0.f;
}
__global__ void k_initseg(int* mx, float* sm, int n) {
    int i = blockIdx.x * blockDim.x + threadIdx.x;
    if (i < n) { mx[i] = 0x80000000; sm[i] = 0.f; }
}

// ---------------- degree / norm ----------------------------------------------
__global__ void k_deg(const int* __restrict__ dst, float* deg, int ne) {
    int e = blockIdx.x * blockDim.x + threadIdx.x;
    if (e < ne) atomicAdd(&deg[dst[e]], 1.f);
}
__global__ void k_dinv(const float* __restrict__ deg, float* dinv, int n) {
    int i = blockIdx.x * blockDim.x + threadIdx.x;
    if (i < n) { float d = deg[i]; dinv[i] = d > 0.f ? rsqrtf(d) : 0.f; }
}
__global__ void k_enorm(const int* __restrict__ js, const int* __restrict__ is,
                        const float* __restrict__ dinv, float* en, int ne) {
    int e = blockIdx.x * blockDim.x + threadIdx.x;
    if (e < ne) en[e] = dinv[js[e]] * dinv[is[e]];
}

// ---------------- GEMM: Out[n,m] = X[n,K] @ W[m,K]^T (+bias) -----------------
// 64x64 tile, k-major smem, float4 LDS, 4x4 microtile.
__global__ void k_gemm_xwt(const float* __restrict__ X, const float* __restrict__ W,
                           const float* __restrict__ bias, float* __restrict__ Out,
                           int n, int K, int m) {
    __shared__ float Xs[16][68];
    __shared__ float Ws[16][68];
    const int tx = threadIdx.x, ty = threadIdx.y;     // 16 x 16
    const int tid = ty * 16 + tx;
    const int rb = blockIdx.y * 64, cb = blockIdx.x * 64;
    float acc[4][4];
#pragma unroll
    for (int i = 0; i < 4; i++)
#pragma unroll
        for (int j = 0; j < 4; j++) acc[i][j] = 0.f;

    for (int k0 = 0; k0 < K; k0 += 16) {
#pragma unroll
        for (int l = 0; l < 4; l++) {
            int el = tid + l * 256;          // 0..1023 -> 64 rows x 16 k
            int r = el >> 4, c = el & 15;
            int gr = rb + r, gc = k0 + c;
            Xs[c][r] = (gr < n && gc < K) ? X[(size_t)gr * K + gc] : 0.f;
            int wr = cb + r;
            Ws[c][r] = (wr < m && gc < K) ? W[(size_t)wr * K + gc] : 0.f;
        }
        __syncthreads();
#pragma unroll
        for (int kk = 0; kk < 16; kk++) {
            float4 a = *reinterpret_cast<const float4*>(&Xs[kk][ty * 4]);
            float4 b = *reinterpret_cast<const float4*>(&Ws[kk][tx * 4]);
            acc[0][0] += a.x * b.x; acc[0][1] += a.x * b.y; acc[0][2] += a.x * b.z; acc[0][3] += a.x * b.w;
            acc[1][0] += a.y * b.x; acc[1][1] += a.y * b.y; acc[1][2] += a.y * b.z; acc[1][3] += a.y * b.w;
            acc[2][0] += a.z * b.x; acc[2][1] += a.z * b.y; acc[2][2] += a.z * b.z; acc[2][3] += a.z * b.w;
            acc[3][0] += a.w * b.x; acc[3][1] += a.w * b.y; acc[3][2] += a.w * b.z; acc[3][3] += a.w * b.w;
        }
        __syncthreads();
    }
#pragma unroll
    for (int i = 0; i < 4; i++)
#pragma unroll
        for (int j = 0; j < 4; j++) {
            int r = rb + ty * 4 + i, c = cb + tx * 4 + j;
            if (r < n && c < m) {
                float v = acc[i][j];
                if (bias) v += bias[c];
                Out[(size_t)r * m + c] = v;
            }
        }
}

// ---- weighted scatter-add: out[dst[e], ofs:ofs+D] += w[e]*X[src[e],:D] ------
// D % 4 == 0 and all row bases 16B-aligned -> red.v4 (4x fewer L2 atomics).
__global__ void k_wagg(const int* __restrict__ srcIdx, const int* __restrict__ dstIdx,
                       const float* __restrict__ w, const float* __restrict__ X,
                       int ss, float* out, int os, int ofs, int D, int ne) {
    int e    = (int)((blockIdx.x * (long long)blockDim.x + threadIdx.x) >> 5);
    int lane = threadIdx.x & 31;
    if (e >= ne) return;
    float wt = w[e];
    const float4* src = reinterpret_cast<const float4*>(X + (size_t)srcIdx[e] * ss);
    float* dst = out + (size_t)dstIdx[e] * os + ofs;
    int D4 = D >> 2;
    for (int c = lane; c < D4; c += 32) {
        float4 v = src[c];
        red4(dst + c * 4, wt * v.x, wt * v.y, wt * v.z, wt * v.w);
    }
}

// ---------------- highway combine: out = sig(gate)*x2' + (1-sig)*xin ---------
__global__ void k_highway(const float* __restrict__ xin, const float* __restrict__ x2,
                          const float* __restrict__ gate, float* out, long long n, int relu2) {
    long long i = blockIdx.x * (long long)blockDim.x + threadIdx.x;
    if (i >= n) return;
    float g = 1.f / (1.f + expf(-gate[i]));
    float b = x2[i];
    if (relu2) b = fmaxf(b, 0.f);
    out[i] = g * b + (1.f - g) * xin[i];
}

// ---------------- segment softmax primitives ---------------------------------
__global__ void k_maxval(const float* __restrict__ val, const int* __restrict__ seg,
                         int* mx, int ne) {
    int e = blockIdx.x * blockDim.x + threadIdx.x;
    if (e < ne) atomicMax(&mx[seg[e]], encf(val[e]));
}
__global__ void k_expval(const float* __restrict__ vin, float* pout,
                         const int* __restrict__ seg, const int* __restrict__ mx,
                         float* sm, int ne) {
    int e = blockIdx.x * blockDim.x + threadIdx.x;
    if (e >= ne) return;
    float p = expf(vin[e] - decf(mx[seg[e]]));
    pout[e] = p;
    atomicAdd(&sm[seg[e]], p);
}
__global__ void k_div(float* p, const int* __restrict__ seg,
                      const float* __restrict__ sm, int ne) {
    int e = blockIdx.x * blockDim.x + threadIdx.x;
    if (e < ne) p[e] = p[e] / (sm[seg[e]] + 1e-16f);
}
__global__ void k_add(const float* a, const float* b, float* o, int ne) {
    int e = blockIdx.x * blockDim.x + threadIdx.x;
    if (e < ne) o[e] = a[e] + b[e];
}

// GAT-style edge score: v = pa[ia] + pb[ib] (+ pc[ic]); leaky_relu; store + seg-max
__global__ void k_score(const float* __restrict__ pa, const int* __restrict__ ia,
                        const float* __restrict__ pb, const int* __restrict__ ib,
                        const float* __restrict__ pc, const int* __restrict__ ic,
                        const int* __restrict__ seg, float* out, int* mx, int ne) {
    int e = blockIdx.x * blockDim.x + threadIdx.x;
    if (e >= ne) return;
    float v = pa[ia[e]] + pb[ib[e]];
    if (pc) v += pc[ic[e]];
    v = v >= 0.f ? v : 0.01f * v;
    out[e] = v;
    atomicMax(&mx[seg[e]], encf(v));
}

// ---------------- relu / strided copies --------------------------------------
__global__ void k_relu(float* p, long long n) {
    long long i = blockIdx.x * (long long)blockDim.x + threadIdx.x;
    if (i < n) p[i] = fmaxf(p[i], 0.f);
}
__global__ void k_zero_str(float* out, int rows, int rstride, int ofs, int D) {
    long long i = blockIdx.x * (long long)blockDim.x + threadIdx.x;
    long long n = (long long)rows * D;
    if (i >= n) return;
    int r = (int)(i / D), c = (int)(i % D);
    out[(size_t)r * rstride + ofs + c] = 0.f;
}
__global__ void k_relu_str(float* out, int rows, int rstride, int ofs, int D) {
    long long i = blockIdx.x * (long long)blockDim.x + threadIdx.x;
    long long n = (long long)rows * D;
    if (i >= n) return;
    int r = (int)(i / D), c = (int)(i % D);
    size_t p = (size_t)r * rstride + ofs + c;
    out[p] = fmaxf(out[p], 0.f);
}
__global__ void k_copy_str(float* out, const float* __restrict__ src,
                           int rows, int rstride, int ofs, int D) {
    long long i = blockIdx.x * (long long)blockDim.x + threadIdx.x;
    long long n = (long long)rows * D;
    if (i >= n) return;
    int r = (int)(i / D), c = (int)(i % D);
    out[(size_t)r * rstride + ofs + c] = src[(size_t)r * D + c];
}

// ---------------- per-row dot products (warp per row) ------------------------
__global__ void k_dot2(const float* __restrict__ X, int stride,
                       const float* __restrict__ a, const float* __restrict__ b,
                       float* outA, float* outB, int n, int D) {
    int w    = (int)((blockIdx.x * (long long)blockDim.x + threadIdx.x) >> 5);
    int lane = threadIdx.x & 31;
    if (w >= n) return;
    const float* row = X + (size_t)w * stride;
    float sa = 0.f, sb = 0.f;
    for (int c = lane; c < D; c += 32) {
        float x = row[c];
        sa += x * a[c];
        if (b) sb += x * b[c];
    }
#pragma unroll
    for (int o = 16; o; o >>= 1) {
        sa += __shfl_down_sync(0xffffffffu, sa, o);
        if (b) sb += __shfl_down_sync(0xffffffffu, sb, o);
    }
    if (lane == 0) { outA[w] = sa; if (b) outB[w] = sb; }
}

// proj over rel_emb = concat([rel_cat, rel_cat], axis=0), rel_cat = [merge|tri]
__global__ void k_projR2(const float* __restrict__ relA, const float* __restrict__ relB,
                         const float* __restrict__ ar, float* out) {
    int w    = (int)((blockIdx.x * (long long)blockDim.x + threadIdx.x) >> 5);
    int lane = threadIdx.x & 31;
    if (w >= 2 * RRR) return;
    int r = w < RRR ? w : w - RRR;
    float s = 0.f;
    for (int c = lane; c < RH; c += 32)
        s += relA[(size_t)r * RH + c] * ar[c] + relB[(size_t)r * RH + c] * ar[RH + c];
#pragma unroll
    for (int o = 16; o; o >>= 1) s += __shfl_down_sync(0xffffffffu, s, o);
    if (lane == 0) out[w] = s;
}

// ---------------- host orchestration -----------------------------------------
static inline int divup(long long a, int b) { return (int)((a + b - 1) / b); }

extern "C" void kernel_launch(void* const* d_in, const int* in_sizes, int n_in,
                              void* d_out, int out_size) {
    const float* x_e      = (const float*)d_in[0];
    const float* merge_v  = (const float*)d_in[1];
    const float* tri_v    = (const float*)d_in[2];
    const float* gcn1_w   = (const float*)d_in[3];
    const float* hw1_w    = (const float*)d_in[4];
    const float* hw1_b    = (const float*)d_in[5];
    const float* gcn2_w   = (const float*)d_in[6];
    const float* hw2_w    = (const float*)d_in[7];
    const float* hw2_b    = (const float*)d_in[8];
    const float* rel_out1 = (const float*)d_in[9];
    const float* rel_tri1 = (const float*)d_in[10];
    const float* hwr_w    = (const float*)d_in[11];
    const float* hwr_b    = (const float*)d_in[12];
    const float* gat_ai   = (const float*)d_in[13];
    const float* gat_aj   = (const float*)d_in[14];
    const float* gat_ar   = (const float*)d_in[15];
    const float* g2e_ah   = (const float*)d_in[16];
    const float* g2e_at   = (const float*)d_in[17];
    const float* g2e_ar   = (const float*)d_in[18];
    const int*   ei       = (const int*)d_in[19];   // [2,E]  rows: h, t
    const int*   rel      = (const int*)d_in[20];   // [E]
    const int*   eia      = (const int*)d_in[21];   // [2,EA] rows: j, i
    const int*   rel_all  = (const int*)d_in[22];   // [EA]
    const int*   lgm      = (const int*)d_in[23];   // [2,LG]
    const int*   lgt      = (const int*)d_in[24];   // [2,LG]
    float*       out      = (float*)d_out;

    // resolve scratch symbols
    float *px, *pt, *pagg, *pdeg, *pdinv, *penorm, *ppA, *ppB, *psm, *pew;
    float *pvi, *pvj, *pv2, *pal, *prsm, *prelA, *prelB, *prgate, *pxr, *pR2, *pR3;
    int *pmx, *prmx;
    cudaGetSymbolAddress((void**)&px, g_x);       cudaGetSymbolAddress((void**)&pt, g_t);
    cudaGetSymbolAddress((void**)&pagg, g_agg);   cudaGetSymbolAddress((void**)&pdeg, g_deg);
    cudaGetSymbolAddress((void**)&pdinv, g_dinv); cudaGetSymbolAddress((void**)&penorm, g_enorm);
    cudaGetSymbolAddress((void**)&ppA, g_pA);     cudaGetSymbolAddress((void**)&ppB, g_pB);
    cudaGetSymbolAddress((void**)&pmx, g_mx);     cudaGetSymbolAddress((void**)&psm, g_sm);
    cudaGetSymbolAddress((void**)&pew, g_ew);
    cudaGetSymbolAddress((void**)&pvi, g_vi);     cudaGetSymbolAddress((void**)&pvj, g_vj);
    cudaGetSymbolAddress((void**)&pv2, g_v2);     cudaGetSymbolAddress((void**)&pal, g_al);
    cudaGetSymbolAddress((void**)&prmx, g_rmx);   cudaGetSymbolAddress((void**)&prsm, g_rsm);
    cudaGetSymbolAddress((void**)&prelA, g_relA); cudaGetSymbolAddress((void**)&prelB, g_relB);
    cudaGetSymbolAddress((void**)&prgate, g_rgate); cudaGetSymbolAddress((void**)&pxr, g_xr);
    cudaGetSymbolAddress((void**)&pR2, g_projR2); cudaGetSymbolAddress((void**)&pR3, g_projR3);

    const int* eia_j = eia;            // sources
    const int* eia_i = eia + EA;       // destinations
    const int* ei_h  = ei;
    const int* ei_t  = ei + EE;

    dim3 gemmT(16, 16);
    dim3 gemmGbig(divup(DD, 64), divup(NN, 64));   // 5 x 1563
    dim3 gemmGrel(divup(RH, 64), divup(RRR, 64));  // 2 x 32

    // ---------- degrees & per-edge gcn norm (shared by both layers) ----------
    k_zero<<<divup(NN, TPB), TPB>>>(pdeg, NN);
    k_deg<<<divup(EA, TPB), TPB>>>(eia_i, pdeg, EA);
    k_dinv<<<divup(NN, TPB), TPB>>>(pdeg, pdinv, NN);
    k_enorm<<<divup(EA, TPB), TPB>>>(eia_j, eia_i, pdinv, penorm, EA);

    const long long ND = (long long)NN * DD;
    const int aggBlocks = divup((long long)EA * 32, TPB);

    // ---------- GCN layer 1 + highway ----------
    k_gemm_xwt<<<gemmGbig, gemmT>>>(x_e, gcn1_w, nullptr, pt, NN, DD, DD);
    k_zero<<<divup(ND, TPB), TPB>>>(pagg, ND);
    k_wagg<<<aggBlocks, TPB>>>(eia_j, eia_i, penorm, pt, DD, pagg, DD, 0, DD, EA);
    k_gemm_xwt<<<gemmGbig, gemmT>>>(x_e, hw1_w, hw1_b, pt, NN, DD, DD);
    k_highway<<<divup(ND, TPB), TPB>>>(x_e, pagg, pt, px, ND, 1);

    // ---------- GCN layer 2 + highway ----------
    k_gemm_xwt<<<gemmGbig, gemmT>>>(px, gcn2_w, nullptr, pt, NN, DD, DD);
    k_zero<<<divup(ND, TPB), TPB>>>(pagg, ND);
    k_wagg<<<aggBlocks, TPB>>>(eia_j, eia_i, penorm, pt, DD, pagg, DD, 0, DD, EA);
    k_gemm_xwt<<<gemmGbig, gemmT>>>(px, hw2_w, hw2_b, pt, NN, DD, DD);
    k_highway<<<divup(ND, TPB), TPB>>>(px, pagg, pt, px, ND, 1);

    // ---------- l_gat (merge and triangular) ----------
    const float* lg_x[2]   = { rel_out1, rel_tri1 };
    const int*   lg_ei[2]  = { lgm, lgt };
    const float* lg_val[2] = { merge_v, tri_v };
    float*       lg_out[2] = { prelA, prelB };
    for (int q = 0; q < 2; q++) {
        const int* lj = lg_ei[q];         // row 0 = j
        const int* li = lg_ei[q] + LG;    // row 1 = i
        const float* val = lg_val[q];
        // vi = softmax over i
        k_initseg<<<divup(RRR, TPB), TPB>>>(prmx, prsm, RRR);
        k_maxval<<<divup(LG, TPB), TPB>>>(val, li, prmx, LG);
        k_expval<<<divup(LG, TPB), TPB>>>(val, pvi, li, prmx, prsm, LG);
        k_div  <<<divup(LG, TPB), TPB>>>(pvi, li, prsm, LG);
        // vj = softmax over j
        k_initseg<<<divup(RRR, TPB), TPB>>>(prmx, prsm, RRR);
        k_maxval<<<divup(LG, TPB), TPB>>>(val, lj, prmx, LG);
        k_expval<<<divup(LG, TPB), TPB>>>(val, pvj, lj, prmx, prsm, LG);
        k_div  <<<divup(LG, TPB), TPB>>>(pvj, lj, prsm, LG);
        // alpha = softmax(vi+vj) over j
        k_add  <<<divup(LG, TPB), TPB>>>(pvi, pvj, pv2, LG);
        k_initseg<<<divup(RRR, TPB), TPB>>>(prmx, prsm, RRR);
        k_maxval<<<divup(LG, TPB), TPB>>>(pv2, lj, prmx, LG);
        k_expval<<<divup(LG, TPB), TPB>>>(pv2, pal, lj, prmx, prsm, LG);
        k_div  <<<divup(LG, TPB), TPB>>>(pal, lj, prsm, LG);
        // out[i] = relu(sum alpha * x[j])
        k_zero <<<divup((long long)RRR * RH, TPB), TPB>>>(lg_out[q], (long long)RRR * RH);
        k_wagg <<<divup((long long)LG * 32, TPB), TPB>>>(lj, li, pal, lg_x[q], RH,
                                                         lg_out[q], RH, 0, RH, LG);
        k_relu <<<divup((long long)RRR * RH, TPB), TPB>>>(lg_out[q], (long long)RRR * RH);
    }

    // ---------- x_r = highway(rel_merge, rel_tri) ----------
    k_gemm_xwt<<<gemmGrel, gemmT>>>(prelA, hwr_w, hwr_b, prgate, RRR, RH, RH);
    k_highway<<<divup((long long)RRR * RH, TPB), TPB>>>(prelA, prelB, prgate, pxr,
                                                       (long long)RRR * RH, 0);

    // ---------- entity GAT ----------
    k_dot2<<<divup((long long)NN * 32, TPB), TPB>>>(px, DD, gat_ai, gat_aj, ppA, ppB, NN, DD);
    k_projR2<<<divup((long long)2 * RRR * 32, TPB), TPB>>>(prelA, prelB, gat_ar, pR2);
    k_initseg<<<divup(NN, TPB), TPB>>>(pmx, psm, NN);
    k_score<<<divup(EA, TPB), TPB>>>(ppA, eia_i, ppB, eia_j, pR2, rel_all, eia_i, pew, pmx, EA);
    k_expval<<<divup(EA, TPB), TPB>>>(pew, pew, eia_i, pmx, psm, EA);
    k_div  <<<divup(EA, TPB), TPB>>>(pew, eia_i, psm, EA);
    // zero out cols 300..799 of d_out, aggregate into 300..599, relu, copy x into 0..299
    k_zero_str<<<divup((long long)NN * 500, TPB), TPB>>>(out, NN, 800, 300, 500);
    k_wagg <<<aggBlocks, TPB>>>(eia_j, eia_i, pew, px, DD, out, 800, 300, DD, EA);
    k_relu_str<<<divup((long long)NN * 300, TPB), TPB>>>(out, NN, 800, 300, 300);
    k_copy_str<<<divup((long long)NN * 300, TPB), TPB>>>(out, px, NN, 800, 0, 300);

    // ---------- relation -> entity GAT ----------
    k_dot2<<<divup((long long)NN * 32, TPB), TPB>>>(out, 800, g2e_ah, g2e_at, ppA, ppB, NN, 600);
    k_dot2<<<divup((long long)RRR * 32, TPB), TPB>>>(pxr, RH, g2e_ar, nullptr, pR3, nullptr, RRR, RH);

    // a1 over h -> cols 600..699
    k_initseg<<<divup(NN, TPB), TPB>>>(pmx, psm, NN);
    k_score<<<divup(EE, TPB), TPB>>>(ppA, ei_h, pR3, rel, nullptr, nullptr, ei_h, pew, pmx, EE);
    k_expval<<<divup(EE, TPB), TPB>>>(pew, pew, ei_h, pmx, psm, EE);
    k_div  <<<divup(EE, TPB), TPB>>>(pew, ei_h, psm, EE);
    k_wagg <<<divup((long long)EE * 32, TPB), TPB>>>(rel, ei_h, pew, pxr, RH, out, 800, 600, RH, EE);

    // a2 over t -> cols 700..799
    k_initseg<<<divup(NN, TPB), TPB>>>(pmx, psm, NN);
    k_score<<<divup(EE, TPB), TPB>>>(ppB, ei_t, pR3, rel, nullptr, nullptr, ei_t, pew, pmx, EE);
    k_expval<<<divup(EE, TPB), TPB>>>(pew, pew, ei_t, pmx, psm, EE);
    k_div  <<<divup(EE, TPB), TPB>>>(pew, ei_t, psm, EE);
    k_wagg <<<divup((long long)EE * 32, TPB), TPB>>>(rel, ei_t, pew, pxr, RH, out, 800, 700, RH, EE);

    (void)in_sizes; (void)n_in; (void)out_size;
}